// round 7
// baseline (speedup 1.0000x reference)
#include <cuda_runtime.h>
#include <cstdint>

#define FULL_MASK 0xFFFFFFFFu
typedef unsigned long long ull;

// ---------------- packed f32x2 helpers (sm_103a) ----------------
__device__ __forceinline__ ull pack2(float lo, float hi) {
    ull r; asm("mov.b64 %0, {%1, %2};" : "=l"(r) : "f"(lo), "f"(hi)); return r;
}
__device__ __forceinline__ void unpack2(ull v, float& lo, float& hi) {
    asm("mov.b64 {%0, %1}, %2;" : "=f"(lo), "=f"(hi) : "l"(v));
}
__device__ __forceinline__ ull ffma2(ull a, ull b, ull c) {
    ull d; asm("fma.rn.f32x2 %0, %1, %2, %3;" : "=l"(d) : "l"(a), "l"(b), "l"(c)); return d;
}

// ---------------- model constants ----------------
__constant__ int FOFF[23] = {0,4,8,12,16,20,24,28,32,36,40,44,48,50,52,53,57,58,59,60,61,62,63};
__constant__ int FDIM[23] = {4,4,4,4,4,4,4,4,4,4,4,4, 2, 2, 1, 4, 1, 1, 1, 1, 1, 1, 2};

static constexpr int OBS  = 65;
static constexpr int NF   = 23;
static constexpr int ZDIM = 230;
static constexpr int HID  = 164;
static constexpr int BATCH = 131072;
static constexpr int ZS   = 232;      // z row stride (pad 230->232)
static constexpr int MS   = 168;      // MLP row stride (pad 164->168)

// packed MLP weights: per layer, [2 halves x 3 slots][KC chunks][32 lanes][4 k]
static constexpr int LOFF1 = 0;               // L1: 192 x 232
static constexpr int LOFF2 = 44544;           // L2..L5: 192 x 168 each
static constexpr int LOFF3 = 76800;
static constexpr int LOFF4 = 109056;
static constexpr int LOFF5 = 141312;
static constexpr int WP_TOTAL = 173568;

__device__ __align__(16) float g_wp[WP_TOTAL];
__device__ __align__(16) float g_bp[5 * 192];
__device__ __align__(16) float g_wh[6 * 168];
__device__ float g_bh[6];
// phase-1 packed weights
__device__ __align__(16) float g_wproj[NF * 10 * 4];  // [tok][e][d], shift-adjusted
__device__ __align__(16) float g_wqkv[10 * 32];       // [d][ q0..9 k0..9 v0..9 0 0 ]
__device__ int g_offadj[32];
// inter-phase activation scratch: [BATCH][232]
__device__ float g_z[(size_t)BATCH * ZS];

// ======================= weight packing kernel =========================
__global__ void pack_kernel(
    const float* __restrict__ W1, const float* __restrict__ W2,
    const float* __restrict__ W3, const float* __restrict__ W4,
    const float* __restrict__ W5,
    const float* __restrict__ b1, const float* __restrict__ b2,
    const float* __restrict__ b3, const float* __restrict__ b4,
    const float* __restrict__ b5,
    const float* __restrict__ Wm, const float* __restrict__ bm,
    const float* __restrict__ Wmk, const float* __restrict__ bmk,
    const float* __restrict__ Wp,
    const float* __restrict__ Wq, const float* __restrict__ Wk,
    const float* __restrict__ Wv)
{
    const int k = blockIdx.x;    // 0..231
    const int l = blockIdx.y;    // 0..7
    const int c = threadIdx.x;   // 0..191
    if (l < 5) {
        const int KPl = (l == 0) ? 232 : 168;
        if (k >= KPl) return;
        const int Kl  = (l == 0) ? 230 : 164;
        const int KCl = KPl / 4;
        const float* Ws = (l == 0) ? W1 : (l == 1) ? W2 : (l == 2) ? W3 : (l == 3) ? W4 : W5;
        const float* bs = (l == 0) ? b1 : (l == 1) ? b2 : (l == 2) ? b3 : (l == 3) ? b4 : b5;
        const int loff  = (l == 0) ? LOFF1 : (l == 1) ? LOFF2 : (l == 2) ? LOFF3
                         : (l == 3) ? LOFF4 : LOFF5;
        const float v = (c < HID && k < Kl) ? Ws[k * HID + c] : 0.f;
        const int h = c / 96, s = (c % 96) / 32, lane = c % 32;
        g_wp[loff + ((h * 3 + s) * KCl + (k >> 2)) * 128 + lane * 4 + (k & 3)] = v;
        if (k == 0) g_bp[l * 192 + c] = (c < HID) ? bs[c] : 0.f;
    } else if (l == 5) {
        if (k >= 168 || c >= 6) return;
        g_wh[c * 168 + k] = (k < HID) ? ((c < 5) ? Wm[k * 5 + c] : Wmk[k]) : 0.f;
        if (k == 0) g_bh[c] = (c < 5) ? bm[c] : bmk[0];
    } else if (l == 6) {
        if (k < ZDIM && c < 4) {
            const int i = k / 10;
            const int off  = FOFF[i];
            const int dim  = FDIM[i];
            const int offa = (off < 61) ? off : 61;
            const int shift = off - offa;
            const int d = c;
            float v = 0.f;
            if (d >= shift && (d - shift) < dim)
                v = Wp[(offa + d) * ZDIM + k];
            g_wproj[k * 4 + d] = v;
        }
        if (c == 4 && k < 32)
            g_offadj[k] = (k < NF) ? ((FOFF[k] < 61) ? FOFF[k] : 61) : 0;
    } else {
        if (k < 10 && c < 32) {
            float v = 0.f;
            if (c < 10)      v = Wq[k * 10 + c];
            else if (c < 20) v = Wk[k * 10 + (c - 10)];
            else if (c < 30) v = Wv[k * 10 + (c - 20)];
            g_wqkv[k * 32 + c] = v;
        }
    }
}

// ======================= Phase 1 kernel: proj + attention ==============
__global__ void __launch_bounds__(256, 2)
phase1_kernel(const float* __restrict__ x, const float* __restrict__ bpj, int B)
{
    __shared__ float kvs[8][576];   // per warp: kb[23][12], vb[23][12]
    const int tid  = threadIdx.x;
    const int w    = tid >> 5;
    const int lane = tid & 31;
    float* kb = kvs[w];
    float* vb = kvs[w] + 288;

    const float inv_sqrt10 = 0.31622776601683794f;
    const int tok = (lane < NF) ? lane : 0;
    const int offa = g_offadj[tok];
    float4 wpj[10];
    float  bq[10];
    #pragma unroll
    for (int e = 0; e < 10; e++) wpj[e] = ((const float4*)g_wproj)[tok * 10 + e];
    {
        const float2* b2 = (const float2*)(bpj + tok * 10);
        #pragma unroll
        for (int u = 0; u < 5; u++) { float2 t = b2[u]; bq[2*u] = t.x; bq[2*u+1] = t.y; }
    }

    const int rowbase = blockIdx.x * 32 + w * 4;

    #pragma unroll 1
    for (int rr = 0; rr < 4; rr++) {
        const int row = rowbase + rr;
        float* zrow = g_z + (size_t)row * ZS;

        const float* xr = x + (long long)row * OBS + offa;
        const float x0 = xr[0], x1 = xr[1], x2 = xr[2], x3 = xr[3];

        float h[10];
        #pragma unroll
        for (int e = 0; e < 10; e++)
            h[e] = fmaf(x3, wpj[e].w, fmaf(x2, wpj[e].z,
                   fmaf(x1, wpj[e].y, fmaf(x0, wpj[e].x, bq[e]))));

        float q[10], kk[10], vv[10];
        #pragma unroll
        for (int e = 0; e < 10; e++) { q[e] = 0.f; kk[e] = 0.f; vv[e] = 0.f; }
        #pragma unroll
        for (int d = 0; d < 10; d++) {
            float wf[32];
            #pragma unroll
            for (int u = 0; u < 8; u++)
                *(float4*)(wf + 4 * u) = ((const float4*)(g_wqkv + d * 32))[u];
            const float hd = h[d];
            #pragma unroll
            for (int e = 0; e < 10; e++) {
                q[e]  = fmaf(hd, wf[e],      q[e]);
                kk[e] = fmaf(hd, wf[10 + e], kk[e]);
                vv[e] = fmaf(hd, wf[20 + e], vv[e]);
            }
        }
        if (lane < NF) {
            float2* ks = (float2*)(kb + tok * 12);
            float2* vs = (float2*)(vb + tok * 12);
            #pragma unroll
            for (int u = 0; u < 5; u++) {
                ks[u] = make_float2(kk[2*u], kk[2*u+1]);
                vs[u] = make_float2(vv[2*u], vv[2*u+1]);
            }
        }
        __syncwarp();

        float ssum = 0.f;
        float ctx[10];
        #pragma unroll
        for (int e = 0; e < 10; e++) ctx[e] = 0.f;
        #pragma unroll
        for (int j = 0; j < NF; j++) {
            const float* kj = kb + j * 12;
            const float4 ka = *(const float4*)kj;
            const float4 kbv = *(const float4*)(kj + 4);
            const float2 kc = *(const float2*)(kj + 8);
            float dt;
            dt = q[0] * ka.x;
            dt = fmaf(q[1], ka.y, dt);
            dt = fmaf(q[2], ka.z, dt);
            dt = fmaf(q[3], ka.w, dt);
            dt = fmaf(q[4], kbv.x, dt);
            dt = fmaf(q[5], kbv.y, dt);
            dt = fmaf(q[6], kbv.z, dt);
            dt = fmaf(q[7], kbv.w, dt);
            dt = fmaf(q[8], kc.x, dt);
            dt = fmaf(q[9], kc.y, dt);
            const float pe = __expf(dt * inv_sqrt10);
            ssum += pe;
            const float* vj = vb + j * 12;
            const float4 va = *(const float4*)vj;
            const float4 vbv = *(const float4*)(vj + 4);
            const float2 vc = *(const float2*)(vj + 8);
            ctx[0] = fmaf(pe, va.x, ctx[0]);
            ctx[1] = fmaf(pe, va.y, ctx[1]);
            ctx[2] = fmaf(pe, va.z, ctx[2]);
            ctx[3] = fmaf(pe, va.w, ctx[3]);
            ctx[4] = fmaf(pe, vbv.x, ctx[4]);
            ctx[5] = fmaf(pe, vbv.y, ctx[5]);
            ctx[6] = fmaf(pe, vbv.z, ctx[6]);
            ctx[7] = fmaf(pe, vbv.w, ctx[7]);
            ctx[8] = fmaf(pe, vc.x, ctx[8]);
            ctx[9] = fmaf(pe, vc.y, ctx[9]);
        }
        const float rs = __fdividef(1.f, ssum);
        if (lane < NF) {
            float2* zs = (float2*)(zrow + tok * 10);
            #pragma unroll
            for (int u = 0; u < 5; u++)
                zs[u] = make_float2(fmaf(ctx[2*u],   rs, h[2*u]),
                                    fmaf(ctx[2*u+1], rs, h[2*u+1]));
        }
        if (lane == NF) { zrow[230] = 0.f; zrow[231] = 0.f; }   // K-pad
        __syncwarp();
    }
}

// ======================= pair GEMM (16 rows x 96 cols per warp) =========
template<int KC, int SSTRIDE>
__device__ __forceinline__ void gemm_pair16(
    const float* __restrict__ bin, float* __restrict__ bout,
    const float* __restrict__ wl, const float* __restrict__ bp,
    int half, int lane, int barid)
{
    ull acc[16][3];
    int c[3];
    #pragma unroll
    for (int s = 0; s < 3; s++) {
        c[s] = 96 * half + 32 * s + lane;
        const ull a0 = pack2(bp[c[s]], 0.f);
        #pragma unroll
        for (int r = 0; r < 16; r++) acc[r][s] = a0;
    }
    const float4* wq0 = ((const float4*)wl) + (half * 3 + 0) * KC * 32 + lane;
    const float4* wq1 = ((const float4*)wl) + (half * 3 + 1) * KC * 32 + lane;
    const float4* wq2 = ((const float4*)wl) + (half * 3 + 2) * KC * 32 + lane;

    #pragma unroll 2
    for (int kc = 0; kc < KC; kc++) {
        const float4 wv0 = wq0[kc * 32];
        const float4 wv1 = wq1[kc * 32];
        const float4 wv2 = wq2[kc * 32];
        const ull* w0 = (const ull*)&wv0;
        const ull* w1 = (const ull*)&wv1;
        const ull* w2 = (const ull*)&wv2;
        #pragma unroll
        for (int r = 0; r < 16; r++) {
            const float4 zv = ((const float4*)(bin + r * SSTRIDE))[kc];  // broadcast
            const ull* zp = (const ull*)&zv;
            acc[r][0] = ffma2(zp[0], w0[0], acc[r][0]);
            acc[r][0] = ffma2(zp[1], w0[1], acc[r][0]);
            acc[r][1] = ffma2(zp[0], w1[0], acc[r][1]);
            acc[r][1] = ffma2(zp[1], w1[1], acc[r][1]);
            acc[r][2] = ffma2(zp[0], w2[0], acc[r][2]);
            acc[r][2] = ffma2(zp[1], w2[1], acc[r][2]);
        }
    }
    #pragma unroll
    for (int s = 0; s < 3; s++) {
        if (c[s] < HID) {
            #pragma unroll
            for (int r = 0; r < 16; r++) {
                float lo, hi; unpack2(acc[r][s], lo, hi);
                bout[r * MS + c[s]] = fmaxf(lo + hi, 0.f);
            }
        }
    }
    asm volatile("bar.sync %0, 64;" :: "r"(barid) : "memory");
}

// ======================= Phase 2 kernel: MLP + heads ====================
// smem per pair: zbuf 16x232 (3712) | m1 16x168 (2688) | m2 16x168 (2688)
static constexpr int PAIR2 = 3712 + 2688 + 2688;   // 9088 floats
static constexpr int SMEM2_FLOATS = 2 * PAIR2;     // 18176 (~72.7 KB)

__global__ void __launch_bounds__(128, 2)
phase2_kernel(float* __restrict__ out, int B)
{
    extern __shared__ float sm[];
    const int tid  = threadIdx.x;
    const int w    = tid >> 5;
    const int lane = tid & 31;
    const int pair = w >> 1;
    const int half = w & 1;
    const int ptid = (tid & 63);        // 0..63 within pair
    const int barid = 1 + pair;

    float* zbuf = sm + pair * PAIR2;
    float* m1   = zbuf + 3712;
    float* m2   = m1 + 2688;

    const int rowbase = blockIdx.x * 32 + pair * 16;

    // load z tile (16 rows x 232 floats, fully coalesced) + zero MLP pads
    {
        const float4* gz = (const float4*)(g_z + (size_t)rowbase * ZS);
        float4* zs = (float4*)zbuf;
        #pragma unroll
        for (int t = ptid; t < 928; t += 64) zs[t] = gz[t];
        #pragma unroll
        for (int t = ptid; t < 128; t += 64) {
            const int buf = t >> 6, r = (t >> 2) & 15, cc = t & 3;
            (buf ? m2 : m1)[r * MS + 164 + cc] = 0.f;
        }
    }
    asm volatile("bar.sync %0, 64;" :: "r"(barid) : "memory");

    gemm_pair16<58, ZS>(zbuf, m1, g_wp + LOFF1, g_bp,       half, lane, barid);
    gemm_pair16<42, MS>(m1,   m2, g_wp + LOFF2, g_bp + 192, half, lane, barid);
    gemm_pair16<42, MS>(m2,   m1, g_wp + LOFF3, g_bp + 384, half, lane, barid);
    gemm_pair16<42, MS>(m1,   m2, g_wp + LOFF4, g_bp + 576, half, lane, barid);
    gemm_pair16<42, MS>(m2,   m1, g_wp + LOFF5, g_bp + 768, half, lane, barid);

    // heads: 16 rows x 6 outputs = 96 items over 64 lanes
    #pragma unroll
    for (int t = ptid; t < 96; t += 64) {
        const int r = t / 6, o = t % 6;
        const float4* zz = (const float4*)(m1 + r * MS);
        const float4* wh = (const float4*)(g_wh + o * 168);
        float4 a4 = make_float4(0.f, 0.f, 0.f, 0.f);
        #pragma unroll 2
        for (int kc = 0; kc < 42; kc++) {
            const float4 z = zz[kc];
            const float4 ww = wh[kc];
            a4.x = fmaf(z.x, ww.x, a4.x);
            a4.y = fmaf(z.y, ww.y, a4.y);
            a4.z = fmaf(z.z, ww.z, a4.z);
            a4.w = fmaf(z.w, ww.w, a4.w);
        }
        const float a = g_bh[o] + ((a4.x + a4.y) + (a4.z + a4.w));
        const int row = rowbase + r;
        if (o < 5) out[row * 5 + o] = a;
        else       out[(long long)B * 5 + row] = a;
    }
}

extern "C" void kernel_launch(void* const* d_in, const int* in_sizes, int n_in,
                              void* d_out, int out_size) {
    const float* x   = (const float*)d_in[0];
    const float* Wp  = (const float*)d_in[1];
    const float* bp  = (const float*)d_in[2];
    const float* Wq  = (const float*)d_in[3];
    const float* Wk  = (const float*)d_in[4];
    const float* Wv  = (const float*)d_in[5];
    const float* W1  = (const float*)d_in[6];
    const float* b1  = (const float*)d_in[7];
    const float* W2  = (const float*)d_in[8];
    const float* b2  = (const float*)d_in[9];
    const float* W3  = (const float*)d_in[10];
    const float* b3  = (const float*)d_in[11];
    const float* W4  = (const float*)d_in[12];
    const float* b4  = (const float*)d_in[13];
    const float* W5  = (const float*)d_in[14];
    const float* b5  = (const float*)d_in[15];
    const float* Wm  = (const float*)d_in[16];
    const float* bm  = (const float*)d_in[17];
    const float* Wmk = (const float*)d_in[18];
    const float* bmk = (const float*)d_in[19];
    float* out = (float*)d_out;

    const int B = in_sizes[0] / OBS;
    const int smem2 = SMEM2_FLOATS * 4;

    cudaFuncSetAttribute(phase2_kernel,
                         cudaFuncAttributeMaxDynamicSharedMemorySize, smem2);

    pack_kernel<<<dim3(232, 8), 192>>>(W1, W2, W3, W4, W5,
                                       b1, b2, b3, b4, b5,
                                       Wm, bm, Wmk, bmk,
                                       Wp, Wq, Wk, Wv);
    phase1_kernel<<<B / 32, 256>>>(x, bp, B);
    phase2_kernel<<<B / 32, 128, smem2>>>(out, B);
}

// round 8
// speedup vs baseline: 1.0323x; 1.0323x over previous
#include <cuda_runtime.h>
#include <cstdint>

#define FULL_MASK 0xFFFFFFFFu
typedef unsigned long long ull;

// ---------------- packed f32x2 helpers (sm_103a) ----------------
__device__ __forceinline__ ull pack2(float lo, float hi) {
    ull r; asm("mov.b64 %0, {%1, %2};" : "=l"(r) : "f"(lo), "f"(hi)); return r;
}
__device__ __forceinline__ void unpack2(ull v, float& lo, float& hi) {
    asm("mov.b64 {%0, %1}, %2;" : "=f"(lo), "=f"(hi) : "l"(v));
}
__device__ __forceinline__ ull ffma2(ull a, ull b, ull c) {
    ull d; asm("fma.rn.f32x2 %0, %1, %2, %3;" : "=l"(d) : "l"(a), "l"(b), "l"(c)); return d;
}

// ---------------- model constants ----------------
__constant__ int FOFF[23] = {0,4,8,12,16,20,24,28,32,36,40,44,48,50,52,53,57,58,59,60,61,62,63};
__constant__ int FDIM[23] = {4,4,4,4,4,4,4,4,4,4,4,4, 2, 2, 1, 4, 1, 1, 1, 1, 1, 1, 2};

static constexpr int OBS  = 65;
static constexpr int NF   = 23;
static constexpr int ZDIM = 230;
static constexpr int HID  = 164;
static constexpr int BATCH = 131072;
static constexpr int ZS   = 232;      // z row stride (pad 230->232)
static constexpr int MS   = 168;      // MLP row stride (pad 164->168)

// packed MLP weights: per layer, [2 halves x 3 slots][KC chunks][32 lanes][4 k]
static constexpr int LOFF1 = 0;               // L1: 192 x 232
static constexpr int LOFF2 = 44544;           // L2..L5: 192 x 168 each
static constexpr int LOFF3 = 76800;
static constexpr int LOFF4 = 109056;
static constexpr int LOFF5 = 141312;
static constexpr int WP_TOTAL = 173568;

__device__ __align__(16) float g_wp[WP_TOTAL];
__device__ __align__(16) float g_bp[5 * 192];
__device__ __align__(16) float g_wh[6 * 168];
__device__ float g_bh[6];
// phase-1 packed weights
__device__ __align__(16) float g_wproj[NF * 10 * 4];  // [tok][e][d], shift-adjusted
__device__ __align__(16) float g_wqkv[10 * 32];       // [d][ q0..9 k0..9 v0..9 0 0 ]
__device__ int g_offadj[32];
// inter-phase activation scratch: [BATCH][232]
__device__ float g_z[(size_t)BATCH * ZS];

// ======================= weight packing kernel =========================
__global__ void pack_kernel(
    const float* __restrict__ W1, const float* __restrict__ W2,
    const float* __restrict__ W3, const float* __restrict__ W4,
    const float* __restrict__ W5,
    const float* __restrict__ b1, const float* __restrict__ b2,
    const float* __restrict__ b3, const float* __restrict__ b4,
    const float* __restrict__ b5,
    const float* __restrict__ Wm, const float* __restrict__ bm,
    const float* __restrict__ Wmk, const float* __restrict__ bmk,
    const float* __restrict__ Wp,
    const float* __restrict__ Wq, const float* __restrict__ Wk,
    const float* __restrict__ Wv)
{
    const int k = blockIdx.x;    // 0..231
    const int l = blockIdx.y;    // 0..7
    const int c = threadIdx.x;   // 0..191
    if (l < 5) {
        const int KPl = (l == 0) ? 232 : 168;
        if (k >= KPl) return;
        const int Kl  = (l == 0) ? 230 : 164;
        const int KCl = KPl / 4;
        const float* Ws = (l == 0) ? W1 : (l == 1) ? W2 : (l == 2) ? W3 : (l == 3) ? W4 : W5;
        const float* bs = (l == 0) ? b1 : (l == 1) ? b2 : (l == 2) ? b3 : (l == 3) ? b4 : b5;
        const int loff  = (l == 0) ? LOFF1 : (l == 1) ? LOFF2 : (l == 2) ? LOFF3
                         : (l == 3) ? LOFF4 : LOFF5;
        const float v = (c < HID && k < Kl) ? Ws[k * HID + c] : 0.f;
        const int h = c / 96, s = (c % 96) / 32, lane = c % 32;
        g_wp[loff + ((h * 3 + s) * KCl + (k >> 2)) * 128 + lane * 4 + (k & 3)] = v;
        if (k == 0) g_bp[l * 192 + c] = (c < HID) ? bs[c] : 0.f;
    } else if (l == 5) {
        if (k >= 168 || c >= 6) return;
        g_wh[c * 168 + k] = (k < HID) ? ((c < 5) ? Wm[k * 5 + c] : Wmk[k]) : 0.f;
        if (k == 0) g_bh[c] = (c < 5) ? bm[c] : bmk[0];
    } else if (l == 6) {
        if (k < ZDIM && c < 4) {
            const int i = k / 10;
            const int off  = FOFF[i];
            const int dim  = FDIM[i];
            const int offa = (off < 61) ? off : 61;
            const int shift = off - offa;
            const int d = c;
            float v = 0.f;
            if (d >= shift && (d - shift) < dim)
                v = Wp[(offa + d) * ZDIM + k];
            g_wproj[k * 4 + d] = v;
        }
        if (c == 4 && k < 32)
            g_offadj[k] = (k < NF) ? ((FOFF[k] < 61) ? FOFF[k] : 61) : 0;
    } else {
        if (k < 10 && c < 32) {
            float v = 0.f;
            if (c < 10)      v = Wq[k * 10 + c];
            else if (c < 20) v = Wk[k * 10 + (c - 10)];
            else if (c < 30) v = Wv[k * 10 + (c - 20)];
            g_wqkv[k * 32 + c] = v;
        }
    }
}

// ======================= Phase 1 kernel: proj + attention ==============
__global__ void __launch_bounds__(256, 2)
phase1_kernel(const float* __restrict__ x, const float* __restrict__ bpj, int B)
{
    __shared__ float kvs[8][576];   // per warp: kb[23][12], vb[23][12]
    const int tid  = threadIdx.x;
    const int w    = tid >> 5;
    const int lane = tid & 31;
    float* kb = kvs[w];
    float* vb = kvs[w] + 288;

    const float inv_sqrt10 = 0.31622776601683794f;
    const int tok = (lane < NF) ? lane : 0;
    const int offa = g_offadj[tok];
    float4 wpj[10];
    float  bq[10];
    #pragma unroll
    for (int e = 0; e < 10; e++) wpj[e] = ((const float4*)g_wproj)[tok * 10 + e];
    {
        const float2* b2 = (const float2*)(bpj + tok * 10);
        #pragma unroll
        for (int u = 0; u < 5; u++) { float2 t = b2[u]; bq[2*u] = t.x; bq[2*u+1] = t.y; }
    }

    const int rowbase = blockIdx.x * 32 + w * 4;

    #pragma unroll 1
    for (int rr = 0; rr < 4; rr++) {
        const int row = rowbase + rr;
        float* zrow = g_z + (size_t)row * ZS;

        const float* xr = x + (long long)row * OBS + offa;
        const float x0 = xr[0], x1 = xr[1], x2 = xr[2], x3 = xr[3];

        float h[10];
        #pragma unroll
        for (int e = 0; e < 10; e++)
            h[e] = fmaf(x3, wpj[e].w, fmaf(x2, wpj[e].z,
                   fmaf(x1, wpj[e].y, fmaf(x0, wpj[e].x, bq[e]))));

        float q[10], kk[10], vv[10];
        #pragma unroll
        for (int e = 0; e < 10; e++) { q[e] = 0.f; kk[e] = 0.f; vv[e] = 0.f; }
        #pragma unroll
        for (int d = 0; d < 10; d++) {
            float wf[32];
            #pragma unroll
            for (int u = 0; u < 8; u++)
                *(float4*)(wf + 4 * u) = ((const float4*)(g_wqkv + d * 32))[u];
            const float hd = h[d];
            #pragma unroll
            for (int e = 0; e < 10; e++) {
                q[e]  = fmaf(hd, wf[e],      q[e]);
                kk[e] = fmaf(hd, wf[10 + e], kk[e]);
                vv[e] = fmaf(hd, wf[20 + e], vv[e]);
            }
        }
        if (lane < NF) {
            float2* ks = (float2*)(kb + tok * 12);
            float2* vs = (float2*)(vb + tok * 12);
            #pragma unroll
            for (int u = 0; u < 5; u++) {
                ks[u] = make_float2(kk[2*u], kk[2*u+1]);
                vs[u] = make_float2(vv[2*u], vv[2*u+1]);
            }
        }
        __syncwarp();

        float ssum = 0.f;
        float ctx[10];
        #pragma unroll
        for (int e = 0; e < 10; e++) ctx[e] = 0.f;
        #pragma unroll
        for (int j = 0; j < NF; j++) {
            const float* kj = kb + j * 12;
            const float4 ka = *(const float4*)kj;
            const float4 kbv = *(const float4*)(kj + 4);
            const float2 kc = *(const float2*)(kj + 8);
            float dt;
            dt = q[0] * ka.x;
            dt = fmaf(q[1], ka.y, dt);
            dt = fmaf(q[2], ka.z, dt);
            dt = fmaf(q[3], ka.w, dt);
            dt = fmaf(q[4], kbv.x, dt);
            dt = fmaf(q[5], kbv.y, dt);
            dt = fmaf(q[6], kbv.z, dt);
            dt = fmaf(q[7], kbv.w, dt);
            dt = fmaf(q[8], kc.x, dt);
            dt = fmaf(q[9], kc.y, dt);
            const float pe = __expf(dt * inv_sqrt10);
            ssum += pe;
            const float* vj = vb + j * 12;
            const float4 va = *(const float4*)vj;
            const float4 vbv = *(const float4*)(vj + 4);
            const float2 vc = *(const float2*)(vj + 8);
            ctx[0] = fmaf(pe, va.x, ctx[0]);
            ctx[1] = fmaf(pe, va.y, ctx[1]);
            ctx[2] = fmaf(pe, va.z, ctx[2]);
            ctx[3] = fmaf(pe, va.w, ctx[3]);
            ctx[4] = fmaf(pe, vbv.x, ctx[4]);
            ctx[5] = fmaf(pe, vbv.y, ctx[5]);
            ctx[6] = fmaf(pe, vbv.z, ctx[6]);
            ctx[7] = fmaf(pe, vbv.w, ctx[7]);
            ctx[8] = fmaf(pe, vc.x, ctx[8]);
            ctx[9] = fmaf(pe, vc.y, ctx[9]);
        }
        const float rs = __fdividef(1.f, ssum);
        if (lane < NF) {
            float2* zs = (float2*)(zrow + tok * 10);
            #pragma unroll
            for (int u = 0; u < 5; u++)
                zs[u] = make_float2(fmaf(ctx[2*u],   rs, h[2*u]),
                                    fmaf(ctx[2*u+1], rs, h[2*u+1]));
        }
        if (lane == NF) { zrow[230] = 0.f; zrow[231] = 0.f; }   // K-pad
        __syncwarp();
    }
}

// ======================= pair GEMM (16 rows x 96 cols per warp) =========
// Output pads (cols 164..167) are written as ZERO so the ping-pong buffer
// is always safe to read at stride MS with K padded to 168.
template<int KC, int SSTRIDE>
__device__ __forceinline__ void gemm_pair16(
    const float* __restrict__ bin, float* __restrict__ bout,
    const float* __restrict__ wl, const float* __restrict__ bp,
    int half, int lane, int barid)
{
    ull acc[16][3];
    int c[3];
    #pragma unroll
    for (int s = 0; s < 3; s++) {
        c[s] = 96 * half + 32 * s + lane;
        const ull a0 = pack2(bp[c[s]], 0.f);
        #pragma unroll
        for (int r = 0; r < 16; r++) acc[r][s] = a0;
    }
    const float4* wq0 = ((const float4*)wl) + (half * 3 + 0) * KC * 32 + lane;
    const float4* wq1 = ((const float4*)wl) + (half * 3 + 1) * KC * 32 + lane;
    const float4* wq2 = ((const float4*)wl) + (half * 3 + 2) * KC * 32 + lane;

    #pragma unroll 2
    for (int kc = 0; kc < KC; kc++) {
        const float4 wv0 = wq0[kc * 32];
        const float4 wv1 = wq1[kc * 32];
        const float4 wv2 = wq2[kc * 32];
        const ull* w0 = (const ull*)&wv0;
        const ull* w1 = (const ull*)&wv1;
        const ull* w2 = (const ull*)&wv2;
        #pragma unroll
        for (int r = 0; r < 16; r++) {
            const float4 zv = ((const float4*)(bin + r * SSTRIDE))[kc];  // broadcast
            const ull* zp = (const ull*)&zv;
            acc[r][0] = ffma2(zp[0], w0[0], acc[r][0]);
            acc[r][0] = ffma2(zp[1], w0[1], acc[r][0]);
            acc[r][1] = ffma2(zp[0], w1[0], acc[r][1]);
            acc[r][1] = ffma2(zp[1], w1[1], acc[r][1]);
            acc[r][2] = ffma2(zp[0], w2[0], acc[r][2]);
            acc[r][2] = ffma2(zp[1], w2[1], acc[r][2]);
        }
    }
    #pragma unroll
    for (int s = 0; s < 3; s++) {
        if (c[s] < 168) {                       // cols 164..167 -> write zero pad
            const bool live = (c[s] < HID);
            #pragma unroll
            for (int r = 0; r < 16; r++) {
                float lo, hi; unpack2(acc[r][s], lo, hi);
                const float v = live ? fmaxf(lo + hi, 0.f) : 0.f;
                bout[r * MS + c[s]] = v;
            }
        }
    }
    asm volatile("bar.sync %0, 64;" :: "r"(barid) : "memory");
}

// ======================= Phase 2 kernel: MLP + heads ====================
// smem per pair: zbuf 16x232 (3712) | m1 16x168 (2688); ping-pong z<->m1.
static constexpr int PAIR2 = 3712 + 2688;          // 6400 floats (25.6 KB)
static constexpr int SMEM2_FLOATS = 2 * PAIR2;     // 12800 (51.2 KB)

__global__ void __launch_bounds__(128, 3)
phase2_kernel(float* __restrict__ out, int B)
{
    extern __shared__ float sm[];
    const int tid  = threadIdx.x;
    const int w    = tid >> 5;
    const int lane = tid & 31;
    const int pair = w >> 1;
    const int half = w & 1;
    const int ptid = (tid & 63);        // 0..63 within pair
    const int barid = 1 + pair;

    float* zbuf = sm + pair * PAIR2;
    float* m1   = zbuf + 3712;

    const int rowbase = blockIdx.x * 32 + pair * 16;

    // load z tile (16 rows x 232 floats, fully coalesced)
    {
        const float4* gz = (const float4*)(g_z + (size_t)rowbase * ZS);
        float4* zs = (float4*)zbuf;
        #pragma unroll
        for (int t = ptid; t < 928; t += 64) zs[t] = gz[t];
    }
    asm volatile("bar.sync %0, 64;" :: "r"(barid) : "memory");

    gemm_pair16<58, ZS>(zbuf, m1,   g_wp + LOFF1, g_bp,       half, lane, barid);
    gemm_pair16<42, MS>(m1,   zbuf, g_wp + LOFF2, g_bp + 192, half, lane, barid);
    gemm_pair16<42, MS>(zbuf, m1,   g_wp + LOFF3, g_bp + 384, half, lane, barid);
    gemm_pair16<42, MS>(m1,   zbuf, g_wp + LOFF4, g_bp + 576, half, lane, barid);
    gemm_pair16<42, MS>(zbuf, m1,   g_wp + LOFF5, g_bp + 768, half, lane, barid);

    // heads: 16 rows x 6 outputs = 96 items over 64 lanes
    #pragma unroll
    for (int t = ptid; t < 96; t += 64) {
        const int r = t / 6, o = t % 6;
        const float4* zz = (const float4*)(m1 + r * MS);
        const float4* wh = (const float4*)(g_wh + o * 168);
        float4 a4 = make_float4(0.f, 0.f, 0.f, 0.f);
        #pragma unroll 2
        for (int kc = 0; kc < 42; kc++) {
            const float4 z = zz[kc];
            const float4 ww = wh[kc];
            a4.x = fmaf(z.x, ww.x, a4.x);
            a4.y = fmaf(z.y, ww.y, a4.y);
            a4.z = fmaf(z.z, ww.z, a4.z);
            a4.w = fmaf(z.w, ww.w, a4.w);
        }
        const float a = g_bh[o] + ((a4.x + a4.y) + (a4.z + a4.w));
        const int row = rowbase + r;
        if (o < 5) out[row * 5 + o] = a;
        else       out[(long long)B * 5 + row] = a;
    }
}

extern "C" void kernel_launch(void* const* d_in, const int* in_sizes, int n_in,
                              void* d_out, int out_size) {
    const float* x   = (const float*)d_in[0];
    const float* Wp  = (const float*)d_in[1];
    const float* bp  = (const float*)d_in[2];
    const float* Wq  = (const float*)d_in[3];
    const float* Wk  = (const float*)d_in[4];
    const float* Wv  = (const float*)d_in[5];
    const float* W1  = (const float*)d_in[6];
    const float* b1  = (const float*)d_in[7];
    const float* W2  = (const float*)d_in[8];
    const float* b2  = (const float*)d_in[9];
    const float* W3  = (const float*)d_in[10];
    const float* b3  = (const float*)d_in[11];
    const float* W4  = (const float*)d_in[12];
    const float* b4  = (const float*)d_in[13];
    const float* W5  = (const float*)d_in[14];
    const float* b5  = (const float*)d_in[15];
    const float* Wm  = (const float*)d_in[16];
    const float* bm  = (const float*)d_in[17];
    const float* Wmk = (const float*)d_in[18];
    const float* bmk = (const float*)d_in[19];
    float* out = (float*)d_out;

    const int B = in_sizes[0] / OBS;
    const int smem2 = SMEM2_FLOATS * 4;

    cudaFuncSetAttribute(phase2_kernel,
                         cudaFuncAttributeMaxDynamicSharedMemorySize, smem2);

    pack_kernel<<<dim3(232, 8), 192>>>(W1, W2, W3, W4, W5,
                                       b1, b2, b3, b4, b5,
                                       Wm, bm, Wmk, bmk,
                                       Wp, Wq, Wk, Wv);
    phase1_kernel<<<B / 32, 256>>>(x, bp, B);
    phase2_kernel<<<B / 32, 128, smem2>>>(out, B);
}

// round 9
// speedup vs baseline: 1.0461x; 1.0133x over previous
#include <cuda_runtime.h>
#include <cstdint>

#define FULL_MASK 0xFFFFFFFFu
typedef unsigned long long ull;

// ---------------- packed f32x2 helpers (sm_103a) ----------------
__device__ __forceinline__ ull pack2(float lo, float hi) {
    ull r; asm("mov.b64 %0, {%1, %2};" : "=l"(r) : "f"(lo), "f"(hi)); return r;
}
__device__ __forceinline__ void unpack2(ull v, float& lo, float& hi) {
    asm("mov.b64 {%0, %1}, %2;" : "=f"(lo), "=f"(hi) : "l"(v));
}
__device__ __forceinline__ ull ffma2(ull a, ull b, ull c) {
    ull d; asm("fma.rn.f32x2 %0, %1, %2, %3;" : "=l"(d) : "l"(a), "l"(b), "l"(c)); return d;
}

// ---------------- model constants ----------------
__constant__ int FOFF[23] = {0,4,8,12,16,20,24,28,32,36,40,44,48,50,52,53,57,58,59,60,61,62,63};
__constant__ int FDIM[23] = {4,4,4,4,4,4,4,4,4,4,4,4, 2, 2, 1, 4, 1, 1, 1, 1, 1, 1, 2};

static constexpr int OBS  = 65;
static constexpr int NF   = 23;
static constexpr int ZDIM = 230;
static constexpr int HID  = 164;
static constexpr int BATCH = 131072;
static constexpr int ZS   = 232;      // z row stride (pad 230->232)
static constexpr int MS   = 168;      // MLP row stride (pad 164->168)

// packed MLP weights: per layer, [2 halves x 3 slots][KC chunks][32 lanes][4 k]
static constexpr int LOFF1 = 0;               // L1: 192 x 232
static constexpr int LOFF2 = 44544;           // L2..L5: 192 x 168 each
static constexpr int LOFF3 = 76800;
static constexpr int LOFF4 = 109056;
static constexpr int LOFF5 = 141312;
static constexpr int WP_TOTAL = 173568;

__device__ __align__(16) float g_wp[WP_TOTAL];
__device__ __align__(16) float g_bp[5 * 192];
__device__ __align__(16) float g_wh[6 * 168];
__device__ float g_bh[6];
// phase-1 packed weights
__device__ __align__(16) float g_wproj[NF * 10 * 4];  // [tok][e][d], shift-adjusted
__device__ __align__(16) float g_wqkv[10 * 32];       // [d][ q0..9 k0..9 v0..9 0 0 ]
__device__ int g_offadj[32];
// inter-phase activation scratch: [BATCH][232]
__device__ float g_z[(size_t)BATCH * ZS];

// ======================= weight packing kernel =========================
__global__ void pack_kernel(
    const float* __restrict__ W1, const float* __restrict__ W2,
    const float* __restrict__ W3, const float* __restrict__ W4,
    const float* __restrict__ W5,
    const float* __restrict__ b1, const float* __restrict__ b2,
    const float* __restrict__ b3, const float* __restrict__ b4,
    const float* __restrict__ b5,
    const float* __restrict__ Wm, const float* __restrict__ bm,
    const float* __restrict__ Wmk, const float* __restrict__ bmk,
    const float* __restrict__ Wp,
    const float* __restrict__ Wq, const float* __restrict__ Wk,
    const float* __restrict__ Wv)
{
    const int k = blockIdx.x;    // 0..231
    const int l = blockIdx.y;    // 0..7
    const int c = threadIdx.x;   // 0..191
    if (l < 5) {
        const int KPl = (l == 0) ? 232 : 168;
        if (k >= KPl) return;
        const int Kl  = (l == 0) ? 230 : 164;
        const int KCl = KPl / 4;
        const float* Ws = (l == 0) ? W1 : (l == 1) ? W2 : (l == 2) ? W3 : (l == 3) ? W4 : W5;
        const float* bs = (l == 0) ? b1 : (l == 1) ? b2 : (l == 2) ? b3 : (l == 3) ? b4 : b5;
        const int loff  = (l == 0) ? LOFF1 : (l == 1) ? LOFF2 : (l == 2) ? LOFF3
                         : (l == 3) ? LOFF4 : LOFF5;
        const float v = (c < HID && k < Kl) ? Ws[k * HID + c] : 0.f;
        const int h = c / 96, s = (c % 96) / 32, lane = c % 32;
        g_wp[loff + ((h * 3 + s) * KCl + (k >> 2)) * 128 + lane * 4 + (k & 3)] = v;
        if (k == 0) g_bp[l * 192 + c] = (c < HID) ? bs[c] : 0.f;
    } else if (l == 5) {
        if (k >= 168 || c >= 6) return;
        g_wh[c * 168 + k] = (k < HID) ? ((c < 5) ? Wm[k * 5 + c] : Wmk[k]) : 0.f;
        if (k == 0) g_bh[c] = (c < 5) ? bm[c] : bmk[0];
    } else if (l == 6) {
        if (k < ZDIM && c < 4) {
            const int i = k / 10;
            const int off  = FOFF[i];
            const int dim  = FDIM[i];
            const int offa = (off < 61) ? off : 61;
            const int shift = off - offa;
            const int d = c;
            float v = 0.f;
            if (d >= shift && (d - shift) < dim)
                v = Wp[(offa + d) * ZDIM + k];
            g_wproj[k * 4 + d] = v;
        }
        if (c == 4 && k < 32)
            g_offadj[k] = (k < NF) ? ((FOFF[k] < 61) ? FOFF[k] : 61) : 0;
    } else {
        if (k < 10 && c < 32) {
            float v = 0.f;
            if (c < 10)      v = Wq[k * 10 + c];
            else if (c < 20) v = Wk[k * 10 + (c - 10)];
            else if (c < 30) v = Wv[k * 10 + (c - 20)];
            g_wqkv[k * 32 + c] = v;
        }
    }
}

// ======================= Phase 1 kernel: proj + attention ==============
// 2 rows interleaved per pass: two independent dependency chains hide
// LDS->FMA->MUFU latency; qkv weight quads amortized over both rows.
__global__ void __launch_bounds__(256, 2)
phase1_kernel(const float* __restrict__ x, const float* __restrict__ bpj, int B)
{
    __shared__ float kvs[8][1152];  // per warp: kb0,vb0,kb1,vb1 each [23][12]
    const int tid  = threadIdx.x;
    const int w    = tid >> 5;
    const int lane = tid & 31;
    float* kb0 = kvs[w];
    float* vb0 = kvs[w] + 288;
    float* kb1 = kvs[w] + 576;
    float* vb1 = kvs[w] + 864;

    const float inv_sqrt10 = 0.31622776601683794f;
    const int tok = (lane < NF) ? lane : 0;
    const int offa = g_offadj[tok];
    float bq[10];
    {
        const float2* b2 = (const float2*)(bpj + tok * 10);
        #pragma unroll
        for (int u = 0; u < 5; u++) { float2 t = b2[u]; bq[2*u] = t.x; bq[2*u+1] = t.y; }
    }

    const int rowbase = blockIdx.x * 32 + w * 4;

    #pragma unroll 1
    for (int pass = 0; pass < 2; pass++) {
        const int row0 = rowbase + 2 * pass;
        const int row1 = row0 + 1;
        float* zrow0 = g_z + (size_t)row0 * ZS;
        float* zrow1 = g_z + (size_t)row1 * ZS;

        const float* xr0 = x + (long long)row0 * OBS + offa;
        const float* xr1 = x + (long long)row1 * OBS + offa;
        const float x00 = xr0[0], x01 = xr0[1], x02 = xr0[2], x03 = xr0[3];
        const float x10 = xr1[0], x11 = xr1[1], x12 = xr1[2], x13 = xr1[3];

        // projection: both rows share each weight quad
        float h0[10], h1[10];
        #pragma unroll
        for (int e = 0; e < 10; e++) {
            const float4 wq = ((const float4*)g_wproj)[tok * 10 + e];
            h0[e] = fmaf(x03, wq.w, fmaf(x02, wq.z, fmaf(x01, wq.y, fmaf(x00, wq.x, bq[e]))));
            h1[e] = fmaf(x13, wq.w, fmaf(x12, wq.z, fmaf(x11, wq.y, fmaf(x10, wq.x, bq[e]))));
        }

        // k,v for both rows (weights shared)
        {
            float kk0[10], vv0[10], kk1[10], vv1[10];
            #pragma unroll
            for (int e = 0; e < 10; e++) { kk0[e]=0.f; vv0[e]=0.f; kk1[e]=0.f; vv1[e]=0.f; }
            #pragma unroll
            for (int d = 0; d < 10; d++) {
                float wf[24];  // floats 8..31 of g_wqkv[d]: k at wf[e+2], v at wf[e+12]
                #pragma unroll
                for (int u = 0; u < 6; u++)
                    *(float4*)(wf + 4 * u) = ((const float4*)(g_wqkv + d * 32))[2 + u];
                const float hd0 = h0[d], hd1 = h1[d];
                #pragma unroll
                for (int e = 0; e < 10; e++) {
                    kk0[e] = fmaf(hd0, wf[e + 2],  kk0[e]);
                    kk1[e] = fmaf(hd1, wf[e + 2],  kk1[e]);
                    vv0[e] = fmaf(hd0, wf[e + 12], vv0[e]);
                    vv1[e] = fmaf(hd1, wf[e + 12], vv1[e]);
                }
            }
            if (lane < NF) {
                float2* ks0 = (float2*)(kb0 + tok * 12);
                float2* vs0 = (float2*)(vb0 + tok * 12);
                float2* ks1 = (float2*)(kb1 + tok * 12);
                float2* vs1 = (float2*)(vb1 + tok * 12);
                #pragma unroll
                for (int u = 0; u < 5; u++) {
                    ks0[u] = make_float2(kk0[2*u], kk0[2*u+1]);
                    vs0[u] = make_float2(vv0[2*u], vv0[2*u+1]);
                    ks1[u] = make_float2(kk1[2*u], kk1[2*u+1]);
                    vs1[u] = make_float2(vv1[2*u], vv1[2*u+1]);
                }
            }
        }

        // q for both rows
        float q0[10], q1[10];
        #pragma unroll
        for (int e = 0; e < 10; e++) { q0[e] = 0.f; q1[e] = 0.f; }
        #pragma unroll
        for (int d = 0; d < 10; d++) {
            float wf[12];  // floats 0..11: q at wf[e]
            #pragma unroll
            for (int u = 0; u < 3; u++)
                *(float4*)(wf + 4 * u) = ((const float4*)(g_wqkv + d * 32))[u];
            const float hd0 = h0[d], hd1 = h1[d];
            #pragma unroll
            for (int e = 0; e < 10; e++) {
                q0[e] = fmaf(hd0, wf[e], q0[e]);
                q1[e] = fmaf(hd1, wf[e], q1[e]);
            }
        }
        __syncwarp();

        // fused logits/exp/ctx for both rows
        float ssum0 = 0.f, ssum1 = 0.f;
        float ctx0[10], ctx1[10];
        #pragma unroll
        for (int e = 0; e < 10; e++) { ctx0[e] = 0.f; ctx1[e] = 0.f; }
        #pragma unroll 1
        for (int j = 0; j < NF; j++) {
            // row 0 logit
            const float* kj0 = kb0 + j * 12;
            const float4 ka0 = *(const float4*)kj0;
            const float4 kb0v = *(const float4*)(kj0 + 4);
            const float2 kc0 = *(const float2*)(kj0 + 8);
            // row 1 logit
            const float* kj1 = kb1 + j * 12;
            const float4 ka1 = *(const float4*)kj1;
            const float4 kb1v = *(const float4*)(kj1 + 4);
            const float2 kc1 = *(const float2*)(kj1 + 8);
            float dt0 = q0[0] * ka0.x;
            float dt1 = q1[0] * ka1.x;
            dt0 = fmaf(q0[1], ka0.y, dt0);  dt1 = fmaf(q1[1], ka1.y, dt1);
            dt0 = fmaf(q0[2], ka0.z, dt0);  dt1 = fmaf(q1[2], ka1.z, dt1);
            dt0 = fmaf(q0[3], ka0.w, dt0);  dt1 = fmaf(q1[3], ka1.w, dt1);
            dt0 = fmaf(q0[4], kb0v.x, dt0); dt1 = fmaf(q1[4], kb1v.x, dt1);
            dt0 = fmaf(q0[5], kb0v.y, dt0); dt1 = fmaf(q1[5], kb1v.y, dt1);
            dt0 = fmaf(q0[6], kb0v.z, dt0); dt1 = fmaf(q1[6], kb1v.z, dt1);
            dt0 = fmaf(q0[7], kb0v.w, dt0); dt1 = fmaf(q1[7], kb1v.w, dt1);
            dt0 = fmaf(q0[8], kc0.x, dt0);  dt1 = fmaf(q1[8], kc1.x, dt1);
            dt0 = fmaf(q0[9], kc0.y, dt0);  dt1 = fmaf(q1[9], kc1.y, dt1);
            const float pe0 = __expf(dt0 * inv_sqrt10);
            const float pe1 = __expf(dt1 * inv_sqrt10);
            ssum0 += pe0;
            ssum1 += pe1;
            const float* vj0 = vb0 + j * 12;
            const float4 va0 = *(const float4*)vj0;
            const float4 vb0v = *(const float4*)(vj0 + 4);
            const float2 vc0 = *(const float2*)(vj0 + 8);
            const float* vj1 = vb1 + j * 12;
            const float4 va1 = *(const float4*)vj1;
            const float4 vb1v = *(const float4*)(vj1 + 4);
            const float2 vc1 = *(const float2*)(vj1 + 8);
            ctx0[0] = fmaf(pe0, va0.x, ctx0[0]);  ctx1[0] = fmaf(pe1, va1.x, ctx1[0]);
            ctx0[1] = fmaf(pe0, va0.y, ctx0[1]);  ctx1[1] = fmaf(pe1, va1.y, ctx1[1]);
            ctx0[2] = fmaf(pe0, va0.z, ctx0[2]);  ctx1[2] = fmaf(pe1, va1.z, ctx1[2]);
            ctx0[3] = fmaf(pe0, va0.w, ctx0[3]);  ctx1[3] = fmaf(pe1, va1.w, ctx1[3]);
            ctx0[4] = fmaf(pe0, vb0v.x, ctx0[4]); ctx1[4] = fmaf(pe1, vb1v.x, ctx1[4]);
            ctx0[5] = fmaf(pe0, vb0v.y, ctx0[5]); ctx1[5] = fmaf(pe1, vb1v.y, ctx1[5]);
            ctx0[6] = fmaf(pe0, vb0v.z, ctx0[6]); ctx1[6] = fmaf(pe1, vb1v.z, ctx1[6]);
            ctx0[7] = fmaf(pe0, vb0v.w, ctx0[7]); ctx1[7] = fmaf(pe1, vb1v.w, ctx1[7]);
            ctx0[8] = fmaf(pe0, vc0.x, ctx0[8]);  ctx1[8] = fmaf(pe1, vc1.x, ctx1[8]);
            ctx0[9] = fmaf(pe0, vc0.y, ctx0[9]);  ctx1[9] = fmaf(pe1, vc1.y, ctx1[9]);
        }
        const float rs0 = __fdividef(1.f, ssum0);
        const float rs1 = __fdividef(1.f, ssum1);
        if (lane < NF) {
            float2* zs0 = (float2*)(zrow0 + tok * 10);
            float2* zs1 = (float2*)(zrow1 + tok * 10);
            #pragma unroll
            for (int u = 0; u < 5; u++) {
                zs0[u] = make_float2(fmaf(ctx0[2*u],   rs0, h0[2*u]),
                                     fmaf(ctx0[2*u+1], rs0, h0[2*u+1]));
                zs1[u] = make_float2(fmaf(ctx1[2*u],   rs1, h1[2*u]),
                                     fmaf(ctx1[2*u+1], rs1, h1[2*u+1]));
            }
        }
        if (lane == NF) {
            zrow0[230] = 0.f; zrow0[231] = 0.f;
            zrow1[230] = 0.f; zrow1[231] = 0.f;
        }
        __syncwarp();
    }
}

// ======================= pair GEMM (16 rows x 96 cols per warp) =========
template<int KC, int SSTRIDE>
__device__ __forceinline__ void gemm_pair16(
    const float* __restrict__ bin, float* __restrict__ bout,
    const float* __restrict__ wl, const float* __restrict__ bp,
    int half, int lane, int barid)
{
    ull acc[16][3];
    int c[3];
    #pragma unroll
    for (int s = 0; s < 3; s++) {
        c[s] = 96 * half + 32 * s + lane;
        const ull a0 = pack2(bp[c[s]], 0.f);
        #pragma unroll
        for (int r = 0; r < 16; r++) acc[r][s] = a0;
    }
    const float4* wq0 = ((const float4*)wl) + (half * 3 + 0) * KC * 32 + lane;
    const float4* wq1 = ((const float4*)wl) + (half * 3 + 1) * KC * 32 + lane;
    const float4* wq2 = ((const float4*)wl) + (half * 3 + 2) * KC * 32 + lane;

    #pragma unroll 2
    for (int kc = 0; kc < KC; kc++) {
        const float4 wv0 = wq0[kc * 32];
        const float4 wv1 = wq1[kc * 32];
        const float4 wv2 = wq2[kc * 32];
        const ull* w0 = (const ull*)&wv0;
        const ull* w1 = (const ull*)&wv1;
        const ull* w2 = (const ull*)&wv2;
        #pragma unroll
        for (int r = 0; r < 16; r++) {
            const float4 zv = ((const float4*)(bin + r * SSTRIDE))[kc];  // broadcast
            const ull* zp = (const ull*)&zv;
            acc[r][0] = ffma2(zp[0], w0[0], acc[r][0]);
            acc[r][0] = ffma2(zp[1], w0[1], acc[r][0]);
            acc[r][1] = ffma2(zp[0], w1[0], acc[r][1]);
            acc[r][1] = ffma2(zp[1], w1[1], acc[r][1]);
            acc[r][2] = ffma2(zp[0], w2[0], acc[r][2]);
            acc[r][2] = ffma2(zp[1], w2[1], acc[r][2]);
        }
    }
    #pragma unroll
    for (int s = 0; s < 3; s++) {
        if (c[s] < 168) {                       // cols 164..167 -> write zero pad
            const bool live = (c[s] < HID);
            #pragma unroll
            for (int r = 0; r < 16; r++) {
                float lo, hi; unpack2(acc[r][s], lo, hi);
                const float v = live ? fmaxf(lo + hi, 0.f) : 0.f;
                bout[r * MS + c[s]] = v;
            }
        }
    }
    asm volatile("bar.sync %0, 64;" :: "r"(barid) : "memory");
}

// ======================= Phase 2 kernel: MLP + heads ====================
static constexpr int PAIR2 = 3712 + 2688;          // 6400 floats (25.6 KB)
static constexpr int SMEM2_FLOATS = 2 * PAIR2;     // 12800 (51.2 KB)

__global__ void __launch_bounds__(128, 3)
phase2_kernel(float* __restrict__ out, int B)
{
    extern __shared__ float sm[];
    const int tid  = threadIdx.x;
    const int w    = tid >> 5;
    const int lane = tid & 31;
    const int pair = w >> 1;
    const int half = w & 1;
    const int ptid = (tid & 63);        // 0..63 within pair
    const int barid = 1 + pair;

    float* zbuf = sm + pair * PAIR2;
    float* m1   = zbuf + 3712;

    const int rowbase = blockIdx.x * 32 + pair * 16;

    // load z tile (16 rows x 232 floats, fully coalesced)
    {
        const float4* gz = (const float4*)(g_z + (size_t)rowbase * ZS);
        float4* zs = (float4*)zbuf;
        #pragma unroll
        for (int t = ptid; t < 928; t += 64) zs[t] = gz[t];
    }
    asm volatile("bar.sync %0, 64;" :: "r"(barid) : "memory");

    gemm_pair16<58, ZS>(zbuf, m1,   g_wp + LOFF1, g_bp,       half, lane, barid);
    gemm_pair16<42, MS>(m1,   zbuf, g_wp + LOFF2, g_bp + 192, half, lane, barid);
    gemm_pair16<42, MS>(zbuf, m1,   g_wp + LOFF3, g_bp + 384, half, lane, barid);
    gemm_pair16<42, MS>(m1,   zbuf, g_wp + LOFF4, g_bp + 576, half, lane, barid);
    gemm_pair16<42, MS>(zbuf, m1,   g_wp + LOFF5, g_bp + 768, half, lane, barid);

    // heads: 16 rows x 6 outputs = 96 items over 64 lanes
    #pragma unroll
    for (int t = ptid; t < 96; t += 64) {
        const int r = t / 6, o = t % 6;
        const float4* zz = (const float4*)(m1 + r * MS);
        const float4* wh = (const float4*)(g_wh + o * 168);
        float4 a4 = make_float4(0.f, 0.f, 0.f, 0.f);
        #pragma unroll 2
        for (int kc = 0; kc < 42; kc++) {
            const float4 z = zz[kc];
            const float4 ww = wh[kc];
            a4.x = fmaf(z.x, ww.x, a4.x);
            a4.y = fmaf(z.y, ww.y, a4.y);
            a4.z = fmaf(z.z, ww.z, a4.z);
            a4.w = fmaf(z.w, ww.w, a4.w);
        }
        const float a = g_bh[o] + ((a4.x + a4.y) + (a4.z + a4.w));
        const int row = rowbase + r;
        if (o < 5) out[row * 5 + o] = a;
        else       out[(long long)B * 5 + row] = a;
    }
}

extern "C" void kernel_launch(void* const* d_in, const int* in_sizes, int n_in,
                              void* d_out, int out_size) {
    const float* x   = (const float*)d_in[0];
    const float* Wp  = (const float*)d_in[1];
    const float* bp  = (const float*)d_in[2];
    const float* Wq  = (const float*)d_in[3];
    const float* Wk  = (const float*)d_in[4];
    const float* Wv  = (const float*)d_in[5];
    const float* W1  = (const float*)d_in[6];
    const float* b1  = (const float*)d_in[7];
    const float* W2  = (const float*)d_in[8];
    const float* b2  = (const float*)d_in[9];
    const float* W3  = (const float*)d_in[10];
    const float* b3  = (const float*)d_in[11];
    const float* W4  = (const float*)d_in[12];
    const float* b4  = (const float*)d_in[13];
    const float* W5  = (const float*)d_in[14];
    const float* b5  = (const float*)d_in[15];
    const float* Wm  = (const float*)d_in[16];
    const float* bm  = (const float*)d_in[17];
    const float* Wmk = (const float*)d_in[18];
    const float* bmk = (const float*)d_in[19];
    float* out = (float*)d_out;

    const int B = in_sizes[0] / OBS;
    const int smem2 = SMEM2_FLOATS * 4;

    cudaFuncSetAttribute(phase2_kernel,
                         cudaFuncAttributeMaxDynamicSharedMemorySize, smem2);

    pack_kernel<<<dim3(232, 8), 192>>>(W1, W2, W3, W4, W5,
                                       b1, b2, b3, b4, b5,
                                       Wm, bm, Wmk, bmk,
                                       Wp, Wq, Wk, Wv);
    phase1_kernel<<<B / 32, 256>>>(x, bp, B);
    phase2_kernel<<<B / 32, 128, smem2>>>(out, B);
}